// round 13
// baseline (speedup 1.0000x reference)
#include <cuda_runtime.h>
#include <cuda_bf16.h>
#include <cstdint>

// VQ lookup via warp-level bf16 mma.sync (HMMA) + fused exact fp32 refinement.
// R12: TWO-pass split  dot ~= zh*ch + zh*cl  (zl pass dropped; error <= 0.6 in
// dist2, TAU=1.5 flags every possibly-wrong row for exact fp32 re-argmin).
// Base structure = R9 (260us, 2 CTAs/SM); only the zl tile/pass removed.

#define D_DIM   510
#define K_CODES 128
#define BM      128
#define KC      64           // K-chunk (elements)
#define NCH     8            // 8*64 = 512, cols 510/511 zeroed
#define TAU     1.5f
#define ST      144          // bf16 tile row stride BYTES (72 bf16)

// smem byte offsets
#define SM_CSQ  0                        // 128 f32
#define SM_KF   512                      // 128 i32
#define SM_FLG  1024                     // 128 i32
#define SM_BV   1536                     // 2*128 f32
#define SM_SV   2560                     // 2*128 f32
#define SM_BK   3584                     // 2*128 i32
#define SM_ZH   4608
#define SM_CH   (SM_ZH + 128*ST)
#define SM_CL   (SM_CH + 128*ST)
#define SMEM_BYTES (SM_CL + 128*ST)      // 59904 -> easily 2 CTAs/SM

__device__ float g_csq[K_CODES];
__device__ __align__(128) __nv_bfloat16 g_cbh[K_CODES * 512];  // 512-padded rows
__device__ __align__(128) __nv_bfloat16 g_cbl[K_CODES * 512];

// ---------------------------------------------------------------- prep: c_sq + cb split
__global__ void prep_kernel(const float* __restrict__ cb) {
    int k = blockIdx.x, tid = threadIdx.x;
    float s = 0.f;
    for (int d = tid; d < 512; d += 256) {
        float v = (d < D_DIM) ? cb[k * D_DIM + d] : 0.f;
        __nv_bfloat16 h = __float2bfloat16(v);
        __nv_bfloat16 l = __float2bfloat16(v - __bfloat162float(h));
        g_cbh[k * 512 + d] = h;
        g_cbl[k * 512 + d] = l;
        s = fmaf(v, v, s);
    }
    #pragma unroll
    for (int off = 16; off; off >>= 1) s += __shfl_xor_sync(0xffffffffu, s, off);
    __shared__ float red[8];
    if ((tid & 31) == 0) red[tid >> 5] = s;
    __syncthreads();
    if (tid == 0) {
        float t = 0.f;
        #pragma unroll
        for (int i = 0; i < 8; i++) t += red[i];
        g_csq[k] = t;
    }
}

// ---------------------------------------------------------------- helpers
__device__ __forceinline__ uint32_t pack2(__nv_bfloat16 a, __nv_bfloat16 b) {
    return (uint32_t)__bfloat16_as_ushort(b) << 16 | (uint32_t)__bfloat16_as_ushort(a);
}
__device__ __forceinline__ void ldm4(uint32_t* r, uint32_t addr) {
    asm volatile("ldmatrix.sync.aligned.m8n8.x4.shared.b16 {%0,%1,%2,%3}, [%4];"
                 : "=r"(r[0]), "=r"(r[1]), "=r"(r[2]), "=r"(r[3]) : "r"(addr));
}
__device__ __forceinline__ void mma16816(float* d, const uint32_t* a,
                                         const uint32_t* b) {
    asm volatile(
        "mma.sync.aligned.m16n8k16.row.col.f32.bf16.bf16.f32 "
        "{%0,%1,%2,%3}, {%4,%5,%6,%7}, {%8,%9}, {%0,%1,%2,%3};"
        : "+f"(d[0]), "+f"(d[1]), "+f"(d[2]), "+f"(d[3])
        : "r"(a[0]), "r"(a[1]), "r"(a[2]), "r"(a[3]), "r"(b[0]), "r"(b[1]));
}
__device__ __forceinline__ void merge2(float& bv, float& sv, int& bk,
                                       float obv, float osv, int obk) {
    if (obv < bv) { sv = fminf(bv, osv); bv = obv; bk = obk; }
    else          { sv = fminf(sv, obv); }
}

extern __shared__ __align__(128) char smem[];

// ---------------------------------------------------------------- main kernel
__global__ __launch_bounds__(256, 2)
void vq_mma_kernel(const float* __restrict__ z,
                   const float* __restrict__ cb,
                   float* __restrict__ out) {
    const uint32_t sbase = (uint32_t)__cvta_generic_to_shared(smem);
    const int tid  = threadIdx.x;
    const int wid  = tid >> 5;
    const int lane = tid & 31;
    const int wr   = wid & 3;       // row group: 4 x 32 rows
    const int wc   = wid >> 2;      // code group: 2 x 64 codes
    const long long row0 = (long long)blockIdx.x * BM;

    if (tid < K_CODES) *(float*)(smem + SM_CSQ + tid * 4) = g_csq[tid];

    const float* zg = z + row0 * D_DIM;

    float acc[2][8][4];
    #pragma unroll
    for (int mt = 0; mt < 2; ++mt)
        #pragma unroll
        for (int nt = 0; nt < 8; ++nt)
            #pragma unroll
            for (int q = 0; q < 4; ++q) acc[mt][nt][q] = 0.f;

    // ldmatrix lane->address geometry (byte offsets within a tile)
    const uint32_t a_off = (uint32_t)((wr * 32 + (lane & 15)) * ST + ((lane >> 4) * 8) * 2);
    const uint32_t b_off = (uint32_t)((wc * 64 + ((lane >> 4) << 3) + (lane & 7)) * ST
                                      + (((lane >> 3) & 1) * 8) * 2);
    // z load/convert geometry: 16 threads per row, 4 floats each
    const int lr0 = tid >> 4;
    const int lkq = (tid & 15) * 4;

    for (int ch = 0; ch < NCH; ++ch) {
        __syncthreads();             // tiles free (prev chunk's mma done)
        const int gk = ch * KC + lkq;
        const bool tail = (gk == 508);

        // ---- z tile: load fp32, round to bf16 hi ONLY (2-pass scheme)
        #pragma unroll
        for (int it = 0; it < 8; ++it) {
            const int r = lr0 + it * 16;
            const uint32_t so = (uint32_t)(r * ST + lkq * 2);
            const float* p = zg + (long long)r * D_DIM + gk;
            float2 a = *(const float2*)p;
            float2 b = tail ? make_float2(0.f, 0.f) : *(const float2*)(p + 2);
            __nv_bfloat16 h0 = __float2bfloat16(a.x);
            __nv_bfloat16 h1 = __float2bfloat16(a.y);
            __nv_bfloat16 h2 = __float2bfloat16(b.x);
            __nv_bfloat16 h3 = __float2bfloat16(b.y);
            *(uint2*)(smem + SM_ZH + so) = make_uint2(pack2(h0,h1), pack2(h2,h3));
        }
        // ---- cb tiles: straight uint4 copy from pre-split global (L2-hot)
        #pragma unroll
        for (int it = 0; it < 4; ++it) {
            const int idx = it * 256 + tid;   // 0..1023
            const int r = idx >> 3;           // code row 0..127
            const int q = idx & 7;            // uint4 slot within 128B
            const int gidx = r * 512 + ch * KC;
            uint4 vh = *((const uint4*)(g_cbh + gidx) + q);
            uint4 vl = *((const uint4*)(g_cbl + gidx) + q);
            *(uint4*)(smem + SM_CH + r * ST + q * 16) = vh;
            *(uint4*)(smem + SM_CL + r * ST + q * 16) = vl;
        }
        __syncthreads();

        // ---- mma over 4 k-steps of 16: zh x (ch, cl)
        #pragma unroll
        for (int ks = 0; ks < 4; ++ks) {
            const uint32_t kb = (uint32_t)(ks * 32);   // 16 bf16 = 32 bytes
            uint32_t ah[2][4];
            #pragma unroll
            for (int mt = 0; mt < 2; ++mt)
                ldm4(ah[mt], sbase + SM_ZH + a_off + (uint32_t)(mt * 16 * ST) + kb);
            #pragma unroll
            for (int np = 0; np < 4; ++np) {           // n-tile pairs
                const uint32_t bo = b_off + (uint32_t)(np * 16 * ST) + kb;
                uint32_t bh[4], bl[4];
                ldm4(bh, sbase + SM_CH + bo);
                ldm4(bl, sbase + SM_CL + bo);
                #pragma unroll
                for (int mt = 0; mt < 2; ++mt) {
                    mma16816(acc[mt][np*2+0], ah[mt], bh + 0);
                    mma16816(acc[mt][np*2+1], ah[mt], bh + 2);
                    mma16816(acc[mt][np*2+0], ah[mt], bl + 0);
                    mma16816(acc[mt][np*2+1], ah[mt], bl + 2);
                }
            }
        }
    }

    // ---- epilogue: top-2 per row
    const float* csq_s = (const float*)(smem + SM_CSQ);
    float* bvp = (float*)(smem + SM_BV);
    float* svp = (float*)(smem + SM_SV);
    int*   bkp = (int*)(smem + SM_BK);
    int*   flg = (int*)(smem + SM_FLG);

    #pragma unroll
    for (int mt = 0; mt < 2; ++mt) {
        #pragma unroll
        for (int rh = 0; rh < 2; ++rh) {
            float bv = 3.4e38f, sv = 3.4e38f;
            int bk = 0;
            #pragma unroll
            for (int nt = 0; nt < 8; ++nt) {
                #pragma unroll
                for (int s = 0; s < 2; ++s) {
                    const int c = wc * 64 + nt * 8 + (lane & 3) * 2 + s;
                    const float d2 = fmaf(-2.f, acc[mt][nt][rh * 2 + s], csq_s[c]);
                    if (d2 < bv) { sv = bv; bv = d2; bk = c; }
                    else if (d2 < sv) sv = d2;
                }
            }
            #pragma unroll
            for (int off = 1; off <= 2; off <<= 1) {
                float obv = __shfl_xor_sync(0xffffffffu, bv, off);
                float osv = __shfl_xor_sync(0xffffffffu, sv, off);
                int   obk = __shfl_xor_sync(0xffffffffu, bk, off);
                merge2(bv, sv, bk, obv, osv, obk);
            }
            if ((lane & 3) == 0) {
                const int r = wr * 32 + mt * 16 + rh * 8 + (lane >> 2);
                bvp[wc * 128 + r] = bv;
                svp[wc * 128 + r] = sv;
                bkp[wc * 128 + r] = bk;
            }
        }
    }
    __syncthreads();

    if (tid < BM) {
        float bv = bvp[tid], sv = svp[tid];
        int bk = bkp[tid];
        merge2(bv, sv, bk, bvp[128 + tid], svp[128 + tid], bkp[128 + tid]);
        *(int*)(smem + SM_KF + tid * 4) = bk;
        flg[tid] = ((sv - bv) < TAU) ? 1 : 0;
    }
    __syncthreads();

    // ---- gather: out[row] = codebook[kfin[row]]
    if (tid < 255) {
        const int dpos = tid * 2;
        float* ob = out + row0 * D_DIM + dpos;
        #pragma unroll 4
        for (int r = 0; r < BM; ++r) {
            int k = *(const int*)(smem + SM_KF + r * 4);
            float2 v = *(const float2*)(cb + k * D_DIM + dpos);
            *(float2*)(ob + (long long)r * D_DIM) = v;
        }
    }
    __syncthreads();

    // ---- fused exact refinement of near-tie rows (~10% of rows at TAU=1.5)
    for (int r = wid; r < BM; r += 8) {
        if (!flg[r]) continue;                      // warp-uniform branch
        const long long row = row0 + r;
        const float* zr = z + row * D_DIM;
        float zreg[16];
        #pragma unroll
        for (int t = 0; t < 16; ++t) {
            int d = lane + t * 32;
            zreg[t] = (d < D_DIM) ? zr[d] : 0.f;
        }
        float bv = 3.4e38f;
        int bk = 0;
        for (int c = 0; c < K_CODES; ++c) {
            const float* cr = cb + c * D_DIM;
            float s = 0.f;
            #pragma unroll
            for (int t = 0; t < 16; ++t) {
                int d = lane + t * 32;
                float cv = (d < D_DIM) ? cr[d] : 0.f;
                s = fmaf(zreg[t], cv, s);
            }
            #pragma unroll
            for (int off = 16; off; off >>= 1)
                s += __shfl_xor_sync(0xffffffffu, s, off);
            float d2 = fmaf(-2.f, s, csq_s[c]);
            if (d2 < bv) { bv = d2; bk = c; }       // strict <: lowest index wins ties
        }
        for (int d = lane; d < D_DIM; d += 32)
            out[row * D_DIM + d] = cb[bk * D_DIM + d];
    }
}

// ---------------------------------------------------------------- launch
extern "C" void kernel_launch(void* const* d_in, const int* in_sizes, int n_in,
                              void* d_out, int out_size) {
    const float* z  = (const float*)d_in[0];
    const float* cb = (const float*)d_in[1];
    float* out = (float*)d_out;

    cudaFuncSetAttribute(vq_mma_kernel, cudaFuncAttributeMaxDynamicSharedMemorySize,
                         SMEM_BYTES);

    const int n_rows  = in_sizes[0] / D_DIM;   // 131072
    const int nblocks = n_rows / BM;           // 1024

    prep_kernel<<<K_CODES, 256>>>(cb);
    vq_mma_kernel<<<nblocks, 256, SMEM_BYTES>>>(z, cb, out);
}

// round 14
// speedup vs baseline: 2.5287x; 2.5287x over previous
#include <cuda_runtime.h>
#include <cuda_bf16.h>
#include <cstdint>

// VQ lookup via warp-level bf16 mma.sync (HMMA) + fused exact fp32 refinement.
//   dot(z,c) ~= zh*ch + zh*cl + zl*ch   (3-pass Dekker split, TAU=0.01)
// R13: merged-phase pipeline. Double-buffered tiles, KC=32 (16 chunks),
// ONE barrier per chunk: MMA(ch) and load/convert(ch+1) live in the same
// barrier-free block so tensor + LSU/ALU pipes interleave inside each warp.
// smem 86.5KB -> still 2 CTAs/SM. MMA accumulation order identical to R9.

#define D_DIM   510
#define K_CODES 128
#define BM      128
#define KC      32           // K-chunk (elements)
#define NCH     16           // 16*32 = 512, cols 510/511 zeroed
#define TAU     0.01f
#define ST      80           // bf16 tile row stride BYTES (40 bf16); 80%16==0, mod32=16

#define TILE    10240        // one 128-row tile: 128*80

// smem byte offsets
#define SM_CSQ  0                        // 128 f32
#define SM_KF   512                      // 128 i32
#define SM_FLG  1024                     // 128 i32
#define SM_BV   1536                     // 2*128 f32
#define SM_SV   2560                     // 2*128 f32
#define SM_BK   3584                     // 2*128 i32
#define SM_ZT   4608                     // z tiles: buf b at +b*2*TILE (zh,+TILE=zl)
#define SM_CT   (SM_ZT + 4*TILE)         // cb tiles: buf b at +b*2*TILE (ch,+TILE=cl)
#define SMEM_BYTES (SM_CT + 4*TILE)      // 86528

__device__ float g_csq[K_CODES];
__device__ __align__(128) __nv_bfloat16 g_cbh[K_CODES * 512];  // 512-padded rows
__device__ __align__(128) __nv_bfloat16 g_cbl[K_CODES * 512];

// ---------------------------------------------------------------- prep: c_sq + cb split
__global__ void prep_kernel(const float* __restrict__ cb) {
    int k = blockIdx.x, tid = threadIdx.x;
    float s = 0.f;
    for (int d = tid; d < 512; d += 256) {
        float v = (d < D_DIM) ? cb[k * D_DIM + d] : 0.f;
        __nv_bfloat16 h = __float2bfloat16(v);
        __nv_bfloat16 l = __float2bfloat16(v - __bfloat162float(h));
        g_cbh[k * 512 + d] = h;
        g_cbl[k * 512 + d] = l;
        s = fmaf(v, v, s);
    }
    #pragma unroll
    for (int off = 16; off; off >>= 1) s += __shfl_xor_sync(0xffffffffu, s, off);
    __shared__ float red[8];
    if ((tid & 31) == 0) red[tid >> 5] = s;
    __syncthreads();
    if (tid == 0) {
        float t = 0.f;
        #pragma unroll
        for (int i = 0; i < 8; i++) t += red[i];
        g_csq[k] = t;
    }
}

// ---------------------------------------------------------------- helpers
__device__ __forceinline__ void split2(float x, __nv_bfloat16& h, __nv_bfloat16& l) {
    h = __float2bfloat16(x);
    l = __float2bfloat16(x - __bfloat162float(h));
}
__device__ __forceinline__ uint32_t pack2(__nv_bfloat16 a, __nv_bfloat16 b) {
    return (uint32_t)__bfloat16_as_ushort(b) << 16 | (uint32_t)__bfloat16_as_ushort(a);
}
__device__ __forceinline__ void cp_async16(uint32_t dst, const void* src) {
    asm volatile("cp.async.ca.shared.global [%0], [%1], 16;" :: "r"(dst), "l"(src));
}
__device__ __forceinline__ void cp_commit() {
    asm volatile("cp.async.commit_group;");
}
template <int N>
__device__ __forceinline__ void cp_wait() {
    asm volatile("cp.async.wait_group %0;" :: "n"(N));
}
__device__ __forceinline__ void ldm4(uint32_t* r, uint32_t addr) {
    asm volatile("ldmatrix.sync.aligned.m8n8.x4.shared.b16 {%0,%1,%2,%3}, [%4];"
                 : "=r"(r[0]), "=r"(r[1]), "=r"(r[2]), "=r"(r[3]) : "r"(addr));
}
__device__ __forceinline__ void mma16816(float* d, const uint32_t* a,
                                         const uint32_t* b) {
    asm volatile(
        "mma.sync.aligned.m16n8k16.row.col.f32.bf16.bf16.f32 "
        "{%0,%1,%2,%3}, {%4,%5,%6,%7}, {%8,%9}, {%0,%1,%2,%3};"
        : "+f"(d[0]), "+f"(d[1]), "+f"(d[2]), "+f"(d[3])
        : "r"(a[0]), "r"(a[1]), "r"(a[2]), "r"(a[3]), "r"(b[0]), "r"(b[1]));
}
__device__ __forceinline__ void merge2(float& bv, float& sv, int& bk,
                                       float obv, float osv, int obk) {
    if (obv < bv) { sv = fminf(bv, osv); bv = obv; bk = obk; }
    else          { sv = fminf(sv, obv); }
}

extern __shared__ __align__(128) char smem[];

// ---------------------------------------------------------------- main kernel
__global__ __launch_bounds__(256, 2)
void vq_mma_kernel(const float* __restrict__ z,
                   const float* __restrict__ cb,
                   float* __restrict__ out) {
    const uint32_t sbase = (uint32_t)__cvta_generic_to_shared(smem);
    const int tid  = threadIdx.x;
    const int wid  = tid >> 5;
    const int lane = tid & 31;
    const int wr   = wid & 3;       // row group: 4 x 32 rows
    const int wc   = wid >> 2;      // code group: 2 x 64 codes
    const long long row0 = (long long)blockIdx.x * BM;

    if (tid < K_CODES) *(float*)(smem + SM_CSQ + tid * 4) = g_csq[tid];

    const float* zg = z + row0 * D_DIM;

    float acc[2][8][4];
    #pragma unroll
    for (int mt = 0; mt < 2; ++mt)
        #pragma unroll
        for (int nt = 0; nt < 8; ++nt)
            #pragma unroll
            for (int q = 0; q < 4; ++q) acc[mt][nt][q] = 0.f;

    // ldmatrix lane->address geometry (byte offsets within a tile)
    const uint32_t a_off = (uint32_t)((wr * 32 + (lane & 15)) * ST + ((lane >> 4) * 8) * 2);
    const uint32_t b_off = (uint32_t)((wc * 64 + ((lane >> 4) << 3) + (lane & 7)) * ST
                                      + (((lane >> 3) & 1) * 8) * 2);
    // z convert geometry: 8 threads per row, 4 floats each (KC=32)
    const int lr0 = tid >> 3;        // 0..31, +32 per iter (4 iters -> 128 rows)
    const int lkq = (tid & 7) * 4;   // 0,4,...,28

    // ---- load/convert chunk cn into buffer bn (z: LDG+cvt+STS; cb: cp.async)
    auto fill = [&](int cn, int bn) {
        const uint32_t zh = sbase + SM_ZT + (uint32_t)bn * (2 * TILE);
        const uint32_t zl = zh + TILE;
        const uint32_t chb = sbase + SM_CT + (uint32_t)bn * (2 * TILE);
        const uint32_t clb = chb + TILE;
        const int gk = cn * KC + lkq;
        const bool tail = (gk == 508);
        // cb first: fire-and-forget L2 fetch
        #pragma unroll
        for (int it = 0; it < 2; ++it) {
            const int idx = it * 256 + tid;   // 0..511
            const int r = idx >> 2;           // code row 0..127
            const int q = idx & 3;            // uint4 slot (row = 64B)
            const uint32_t doff = (uint32_t)(r * ST + q * 16);
            const char* sh = (const char*)g_cbh + ((long long)r * 512 + cn * KC) * 2 + q * 16;
            const char* sl = (const char*)g_cbl + ((long long)r * 512 + cn * KC) * 2 + q * 16;
            cp_async16(chb + doff, sh);
            cp_async16(clb + doff, sl);
        }
        cp_commit();
        // z: direct LDG -> split -> STS
        #pragma unroll
        for (int it = 0; it < 4; ++it) {
            const int r = lr0 + it * 32;
            const uint32_t so = (uint32_t)(r * ST + lkq * 2);
            const float* p = zg + (long long)r * D_DIM + gk;
            float2 a = *(const float2*)p;
            float2 b = tail ? make_float2(0.f, 0.f) : *(const float2*)(p + 2);
            __nv_bfloat16 h0,l0,h1,l1,h2,l2,h3,l3;
            split2(a.x,h0,l0); split2(a.y,h1,l1);
            split2(b.x,h2,l2); split2(b.y,h3,l3);
            *(uint2*)(smem + (zh - sbase) + so) = make_uint2(pack2(h0,h1), pack2(h2,h3));
            *(uint2*)(smem + (zl - sbase) + so) = make_uint2(pack2(l0,l1), pack2(l2,l3));
        }
    };

    // -------- prologue: fill chunk 0 into buf 0
    fill(0, 0);
    cp_wait<0>();
    __syncthreads();

    // -------- mainloop: ONE barrier per chunk; MMA(ch) + fill(ch+1) merged
    for (int ch = 0; ch < NCH; ++ch) {
        const int p  = ch & 1;
        const int cn = (ch + 1 < NCH) ? ch + 1 : NCH - 1;   // clamp: no branch
        const uint32_t zh  = sbase + SM_ZT + (uint32_t)p * (2 * TILE);
        const uint32_t zl  = zh + TILE;
        const uint32_t chb = sbase + SM_CT + (uint32_t)p * (2 * TILE);
        const uint32_t clb = chb + TILE;

        // fill next chunk (targets buf p^1; no hazard with MMA reads of buf p)
        fill(cn, p ^ 1);

        // MMA over 2 k-steps of 16 (same accumulation sequence as R9)
        #pragma unroll
        for (int ks = 0; ks < 2; ++ks) {
            const uint32_t kb = (uint32_t)(ks * 32);   // 16 bf16 = 32 bytes
            uint32_t ah[2][4], al[2][4];
            #pragma unroll
            for (int mt = 0; mt < 2; ++mt) {
                const uint32_t ao = a_off + (uint32_t)(mt * 16 * ST) + kb;
                ldm4(ah[mt], zh + ao);
                ldm4(al[mt], zl + ao);
            }
            #pragma unroll
            for (int np = 0; np < 4; ++np) {
                const uint32_t bo = b_off + (uint32_t)(np * 16 * ST) + kb;
                uint32_t bh[4], bl[4];
                ldm4(bh, chb + bo);
                ldm4(bl, clb + bo);
                #pragma unroll
                for (int mt = 0; mt < 2; ++mt) {
                    mma16816(acc[mt][np*2+0], ah[mt], bh + 0);
                    mma16816(acc[mt][np*2+1], ah[mt], bh + 2);
                    mma16816(acc[mt][np*2+0], ah[mt], bl + 0);
                    mma16816(acc[mt][np*2+1], ah[mt], bl + 2);
                    mma16816(acc[mt][np*2+0], al[mt], bh + 0);
                    mma16816(acc[mt][np*2+1], al[mt], bh + 2);
                }
            }
        }

        cp_wait<0>();        // cb(ch+1) landed
        __syncthreads();     // z STS(ch+1) + MMA reads(ch) complete everywhere
    }

    // ---- epilogue: top-2 per row
    const float* csq_s = (const float*)(smem + SM_CSQ);
    float* bvp = (float*)(smem + SM_BV);
    float* svp = (float*)(smem + SM_SV);
    int*   bkp = (int*)(smem + SM_BK);
    int*   flg = (int*)(smem + SM_FLG);

    #pragma unroll
    for (int mt = 0; mt < 2; ++mt) {
        #pragma unroll
        for (int rh = 0; rh < 2; ++rh) {
            float bv = 3.4e38f, sv = 3.4e38f;
            int bk = 0;
            #pragma unroll
            for (int nt = 0; nt < 8; ++nt) {
                #pragma unroll
                for (int s = 0; s < 2; ++s) {
                    const int c = wc * 64 + nt * 8 + (lane & 3) * 2 + s;
                    const float d2 = fmaf(-2.f, acc[mt][nt][rh * 2 + s], csq_s[c]);
                    if (d2 < bv) { sv = bv; bv = d2; bk = c; }
                    else if (d2 < sv) sv = d2;
                }
            }
            #pragma unroll
            for (int off = 1; off <= 2; off <<= 1) {
                float obv = __shfl_xor_sync(0xffffffffu, bv, off);
                float osv = __shfl_xor_sync(0xffffffffu, sv, off);
                int   obk = __shfl_xor_sync(0xffffffffu, bk, off);
                merge2(bv, sv, bk, obv, osv, obk);
            }
            if ((lane & 3) == 0) {
                const int r = wr * 32 + mt * 16 + rh * 8 + (lane >> 2);
                bvp[wc * 128 + r] = bv;
                svp[wc * 128 + r] = sv;
                bkp[wc * 128 + r] = bk;
            }
        }
    }
    __syncthreads();

    if (tid < BM) {
        float bv = bvp[tid], sv = svp[tid];
        int bk = bkp[tid];
        merge2(bv, sv, bk, bvp[128 + tid], svp[128 + tid], bkp[128 + tid]);
        *(int*)(smem + SM_KF + tid * 4) = bk;
        flg[tid] = ((sv - bv) < TAU) ? 1 : 0;
    }
    __syncthreads();

    // ---- gather: out[row] = codebook[kfin[row]]
    if (tid < 255) {
        const int dpos = tid * 2;
        float* ob = out + row0 * D_DIM + dpos;
        #pragma unroll 4
        for (int r = 0; r < BM; ++r) {
            int k = *(const int*)(smem + SM_KF + r * 4);
            float2 v = *(const float2*)(cb + k * D_DIM + dpos);
            *(float2*)(ob + (long long)r * D_DIM) = v;
        }
    }
    __syncthreads();

    // ---- fused exact refinement of near-tie rows (~0.2% of rows at TAU=0.01)
    for (int r = wid; r < BM; r += 8) {
        if (!flg[r]) continue;                      // warp-uniform branch
        const long long row = row0 + r;
        const float* zr = z + row * D_DIM;
        float zreg[16];
        #pragma unroll
        for (int t = 0; t < 16; ++t) {
            int d = lane + t * 32;
            zreg[t] = (d < D_DIM) ? zr[d] : 0.f;
        }
        float bv = 3.4e38f;
        int bk = 0;
        for (int c = 0; c < K_CODES; ++c) {
            const float* cr = cb + c * D_DIM;
            float s = 0.f;
            #pragma unroll
            for (int t = 0; t < 16; ++t) {
                int d = lane + t * 32;
                float cv = (d < D_DIM) ? cr[d] : 0.f;
                s = fmaf(zreg[t], cv, s);
            }
            #pragma unroll
            for (int off = 16; off; off >>= 1)
                s += __shfl_xor_sync(0xffffffffu, s, off);
            float d2 = fmaf(-2.f, s, csq_s[c]);
            if (d2 < bv) { bv = d2; bk = c; }       // strict <: lowest index wins ties
        }
        for (int d = lane; d < D_DIM; d += 32)
            out[row * D_DIM + d] = cb[bk * D_DIM + d];
    }
}

// ---------------------------------------------------------------- launch
extern "C" void kernel_launch(void* const* d_in, const int* in_sizes, int n_in,
                              void* d_out, int out_size) {
    const float* z  = (const float*)d_in[0];
    const float* cb = (const float*)d_in[1];
    float* out = (float*)d_out;

    cudaFuncSetAttribute(vq_mma_kernel, cudaFuncAttributeMaxDynamicSharedMemorySize,
                         SMEM_BYTES);

    const int n_rows  = in_sizes[0] / D_DIM;   // 131072
    const int nblocks = n_rows / BM;           // 1024

    prep_kernel<<<K_CODES, 256>>>(cb);
    vq_mma_kernel<<<nblocks, 256, SMEM_BYTES>>>(z, cb, out);
}

// round 15
// speedup vs baseline: 2.5904x; 1.0244x over previous
#include <cuda_runtime.h>
#include <cuda_bf16.h>
#include <cstdint>

// VQ lookup via warp-level bf16 mma.sync (HMMA) + fused exact fp32 refinement.
//   dot(z,c) ~= zh*ch + zh*cl + zl*ch   (3-pass Dekker split, TAU=0.01)
// R14: register-staged pipeline. Per chunk: issue LDG z(ch+1)->regs and
// cp.async cb(ch+1), run MMA(ch) (latency retires under tensor work), THEN
// convert regs->smem. One barrier per chunk. KC=32, double-buffered tiles,
// 86.5KB smem -> 2 CTAs/SM. MMA accumulation order identical to R9.

#define D_DIM   510
#define K_CODES 128
#define BM      128
#define KC      32           // K-chunk (elements)
#define NCH     16           // 16*32 = 512, cols 510/511 zeroed
#define TAU     0.01f
#define ST      80           // bf16 tile row stride BYTES (40 bf16)

#define TILE    10240        // one 128-row tile: 128*80

// smem byte offsets
#define SM_CSQ  0                        // 128 f32
#define SM_KF   512                      // 128 i32
#define SM_FLG  1024                     // 128 i32
#define SM_BV   1536                     // 2*128 f32
#define SM_SV   2560                     // 2*128 f32
#define SM_BK   3584                     // 2*128 i32
#define SM_ZT   4608                     // z tiles: buf b at +b*2*TILE (zh,+TILE=zl)
#define SM_CT   (SM_ZT + 4*TILE)         // cb tiles: buf b at +b*2*TILE (ch,+TILE=cl)
#define SMEM_BYTES (SM_CT + 4*TILE)      // 86528

__device__ float g_csq[K_CODES];
__device__ __align__(128) __nv_bfloat16 g_cbh[K_CODES * 512];  // 512-padded rows
__device__ __align__(128) __nv_bfloat16 g_cbl[K_CODES * 512];

// ---------------------------------------------------------------- prep: c_sq + cb split
__global__ void prep_kernel(const float* __restrict__ cb) {
    int k = blockIdx.x, tid = threadIdx.x;
    float s = 0.f;
    for (int d = tid; d < 512; d += 256) {
        float v = (d < D_DIM) ? cb[k * D_DIM + d] : 0.f;
        __nv_bfloat16 h = __float2bfloat16(v);
        __nv_bfloat16 l = __float2bfloat16(v - __bfloat162float(h));
        g_cbh[k * 512 + d] = h;
        g_cbl[k * 512 + d] = l;
        s = fmaf(v, v, s);
    }
    #pragma unroll
    for (int off = 16; off; off >>= 1) s += __shfl_xor_sync(0xffffffffu, s, off);
    __shared__ float red[8];
    if ((tid & 31) == 0) red[tid >> 5] = s;
    __syncthreads();
    if (tid == 0) {
        float t = 0.f;
        #pragma unroll
        for (int i = 0; i < 8; i++) t += red[i];
        g_csq[k] = t;
    }
}

// ---------------------------------------------------------------- helpers
__device__ __forceinline__ void split2(float x, __nv_bfloat16& h, __nv_bfloat16& l) {
    h = __float2bfloat16(x);
    l = __float2bfloat16(x - __bfloat162float(h));
}
__device__ __forceinline__ uint32_t pack2(__nv_bfloat16 a, __nv_bfloat16 b) {
    return (uint32_t)__bfloat16_as_ushort(b) << 16 | (uint32_t)__bfloat16_as_ushort(a);
}
__device__ __forceinline__ void cp_async16(uint32_t dst, const void* src) {
    asm volatile("cp.async.ca.shared.global [%0], [%1], 16;" :: "r"(dst), "l"(src));
}
__device__ __forceinline__ void cp_commit() {
    asm volatile("cp.async.commit_group;");
}
template <int N>
__device__ __forceinline__ void cp_wait() {
    asm volatile("cp.async.wait_group %0;" :: "n"(N));
}
__device__ __forceinline__ void ldm4(uint32_t* r, uint32_t addr) {
    asm volatile("ldmatrix.sync.aligned.m8n8.x4.shared.b16 {%0,%1,%2,%3}, [%4];"
                 : "=r"(r[0]), "=r"(r[1]), "=r"(r[2]), "=r"(r[3]) : "r"(addr));
}
__device__ __forceinline__ void mma16816(float* d, const uint32_t* a,
                                         const uint32_t* b) {
    asm volatile(
        "mma.sync.aligned.m16n8k16.row.col.f32.bf16.bf16.f32 "
        "{%0,%1,%2,%3}, {%4,%5,%6,%7}, {%8,%9}, {%0,%1,%2,%3};"
        : "+f"(d[0]), "+f"(d[1]), "+f"(d[2]), "+f"(d[3])
        : "r"(a[0]), "r"(a[1]), "r"(a[2]), "r"(a[3]), "r"(b[0]), "r"(b[1]));
}
__device__ __forceinline__ void merge2(float& bv, float& sv, int& bk,
                                       float obv, float osv, int obk) {
    if (obv < bv) { sv = fminf(bv, osv); bv = obv; bk = obk; }
    else          { sv = fminf(sv, obv); }
}

extern __shared__ __align__(128) char smem[];

// ---------------------------------------------------------------- main kernel
__global__ __launch_bounds__(256, 2)
void vq_mma_kernel(const float* __restrict__ z,
                   const float* __restrict__ cb,
                   float* __restrict__ out) {
    const uint32_t sbase = (uint32_t)__cvta_generic_to_shared(smem);
    const int tid  = threadIdx.x;
    const int wid  = tid >> 5;
    const int lane = tid & 31;
    const int wr   = wid & 3;       // row group: 4 x 32 rows
    const int wc   = wid >> 2;      // code group: 2 x 64 codes
    const long long row0 = (long long)blockIdx.x * BM;

    if (tid < K_CODES) *(float*)(smem + SM_CSQ + tid * 4) = g_csq[tid];

    const float* zg = z + row0 * D_DIM;

    float acc[2][8][4];
    #pragma unroll
    for (int mt = 0; mt < 2; ++mt)
        #pragma unroll
        for (int nt = 0; nt < 8; ++nt)
            #pragma unroll
            for (int q = 0; q < 4; ++q) acc[mt][nt][q] = 0.f;

    // ldmatrix lane->address geometry (byte offsets within a tile)
    const uint32_t a_off = (uint32_t)((wr * 32 + (lane & 15)) * ST + ((lane >> 4) * 8) * 2);
    const uint32_t b_off = (uint32_t)((wc * 64 + ((lane >> 4) << 3) + (lane & 7)) * ST
                                      + (((lane >> 3) & 1) * 8) * 2);
    // z load/convert geometry: 8 threads per row, 4 floats each (KC=32)
    const int lr0 = tid >> 3;        // 0..31, +32 per iter (4 iters -> 128 rows)
    const int lkq = (tid & 7) * 4;   // 0,4,...,28

    float2 za[4], zb[4];             // register staging for z(ch+1)

    // ---- issue z LDGs for chunk cn into registers (no consumer here)
    auto ldg_z = [&](int cn) {
        const int gk = cn * KC + lkq;
        const bool tail = (gk == 508);
        #pragma unroll
        for (int it = 0; it < 4; ++it) {
            const int r = lr0 + it * 32;
            const float* p = zg + (long long)r * D_DIM + gk;
            za[it] = *(const float2*)p;
            zb[it] = tail ? make_float2(0.f, 0.f) : *(const float2*)(p + 2);
        }
    };
    // ---- issue cb cp.async for chunk cn into buffer bn
    auto cp_cb = [&](int cn, int bn) {
        const uint32_t chb = sbase + SM_CT + (uint32_t)bn * (2 * TILE);
        const uint32_t clb = chb + TILE;
        #pragma unroll
        for (int it = 0; it < 2; ++it) {
            const int idx = it * 256 + tid;   // 0..511
            const int r = idx >> 2;           // code row 0..127
            const int q = idx & 3;            // uint4 slot (row = 64B)
            const uint32_t doff = (uint32_t)(r * ST + q * 16);
            const char* sh = (const char*)g_cbh + ((long long)r * 512 + cn * KC) * 2 + q * 16;
            const char* sl = (const char*)g_cbl + ((long long)r * 512 + cn * KC) * 2 + q * 16;
            cp_async16(chb + doff, sh);
            cp_async16(clb + doff, sl);
        }
        cp_commit();
    };
    // ---- convert staged registers -> z bf16 tiles in buffer bn
    auto cvt_z = [&](int bn) {
        const uint32_t zho = (uint32_t)(SM_ZT + bn * (2 * TILE));
        #pragma unroll
        for (int it = 0; it < 4; ++it) {
            const int r = lr0 + it * 32;
            const uint32_t so = (uint32_t)(r * ST + lkq * 2);
            __nv_bfloat16 h0,l0,h1,l1,h2,l2,h3,l3;
            split2(za[it].x,h0,l0); split2(za[it].y,h1,l1);
            split2(zb[it].x,h2,l2); split2(zb[it].y,h3,l3);
            *(uint2*)(smem + zho + so)        = make_uint2(pack2(h0,h1), pack2(h2,h3));
            *(uint2*)(smem + zho + TILE + so) = make_uint2(pack2(l0,l1), pack2(l2,l3));
        }
    };

    // -------- prologue: chunk 0 into buf 0
    ldg_z(0);
    cp_cb(0, 0);
    cvt_z(0);
    cp_wait<0>();
    __syncthreads();

    // -------- mainloop: one barrier per chunk
    for (int ch = 0; ch < NCH; ++ch) {
        const int p = ch & 1;
        const bool more = (ch + 1 < NCH);
        const uint32_t zh  = sbase + SM_ZT + (uint32_t)p * (2 * TILE);
        const uint32_t zl  = zh + TILE;
        const uint32_t chb = sbase + SM_CT + (uint32_t)p * (2 * TILE);
        const uint32_t clb = chb + TILE;

        // 1. issue next-chunk loads (no consumers -> no stall)
        if (more) {
            cp_cb(ch + 1, p ^ 1);
            ldg_z(ch + 1);
        }

        // 2. MMA(ch): LDG/L2 latency retires underneath (2 k-steps of 16)
        #pragma unroll
        for (int ks = 0; ks < 2; ++ks) {
            const uint32_t kb = (uint32_t)(ks * 32);
            uint32_t ah[2][4], al[2][4];
            #pragma unroll
            for (int mt = 0; mt < 2; ++mt) {
                const uint32_t ao = a_off + (uint32_t)(mt * 16 * ST) + kb;
                ldm4(ah[mt], zh + ao);
                ldm4(al[mt], zl + ao);
            }
            #pragma unroll
            for (int np = 0; np < 4; ++np) {
                const uint32_t bo = b_off + (uint32_t)(np * 16 * ST) + kb;
                uint32_t bh[4], bl[4];
                ldm4(bh, chb + bo);
                ldm4(bl, clb + bo);
                #pragma unroll
                for (int mt = 0; mt < 2; ++mt) {
                    mma16816(acc[mt][np*2+0], ah[mt], bh + 0);
                    mma16816(acc[mt][np*2+1], ah[mt], bh + 2);
                    mma16816(acc[mt][np*2+0], ah[mt], bl + 0);
                    mma16816(acc[mt][np*2+1], ah[mt], bl + 2);
                    mma16816(acc[mt][np*2+0], al[mt], bh + 0);
                    mma16816(acc[mt][np*2+1], al[mt], bh + 2);
                }
            }
        }

        // 3. consume staged registers (loads have landed by now)
        if (more) {
            cvt_z(p ^ 1);
            cp_wait<0>();
        }
        __syncthreads();   // orders: STS(ch+1) before MMA(ch+1); MMA(ch) reads
                           // before fill(ch+2) overwrites buf p
    }

    // ---- epilogue: top-2 per row
    const float* csq_s = (const float*)(smem + SM_CSQ);
    float* bvp = (float*)(smem + SM_BV);
    float* svp = (float*)(smem + SM_SV);
    int*   bkp = (int*)(smem + SM_BK);
    int*   flg = (int*)(smem + SM_FLG);

    #pragma unroll
    for (int mt = 0; mt < 2; ++mt) {
        #pragma unroll
        for (int rh = 0; rh < 2; ++rh) {
            float bv = 3.4e38f, sv = 3.4e38f;
            int bk = 0;
            #pragma unroll
            for (int nt = 0; nt < 8; ++nt) {
                #pragma unroll
                for (int s = 0; s < 2; ++s) {
                    const int c = wc * 64 + nt * 8 + (lane & 3) * 2 + s;
                    const float d2 = fmaf(-2.f, acc[mt][nt][rh * 2 + s], csq_s[c]);
                    if (d2 < bv) { sv = bv; bv = d2; bk = c; }
                    else if (d2 < sv) sv = d2;
                }
            }
            #pragma unroll
            for (int off = 1; off <= 2; off <<= 1) {
                float obv = __shfl_xor_sync(0xffffffffu, bv, off);
                float osv = __shfl_xor_sync(0xffffffffu, sv, off);
                int   obk = __shfl_xor_sync(0xffffffffu, bk, off);
                merge2(bv, sv, bk, obv, osv, obk);
            }
            if ((lane & 3) == 0) {
                const int r = wr * 32 + mt * 16 + rh * 8 + (lane >> 2);
                bvp[wc * 128 + r] = bv;
                svp[wc * 128 + r] = sv;
                bkp[wc * 128 + r] = bk;
            }
        }
    }
    __syncthreads();

    if (tid < BM) {
        float bv = bvp[tid], sv = svp[tid];
        int bk = bkp[tid];
        merge2(bv, sv, bk, bvp[128 + tid], svp[128 + tid], bkp[128 + tid]);
        *(int*)(smem + SM_KF + tid * 4) = bk;
        flg[tid] = ((sv - bv) < TAU) ? 1 : 0;
    }
    __syncthreads();

    // ---- gather: out[row] = codebook[kfin[row]]
    if (tid < 255) {
        const int dpos = tid * 2;
        float* ob = out + row0 * D_DIM + dpos;
        #pragma unroll 4
        for (int r = 0; r < BM; ++r) {
            int k = *(const int*)(smem + SM_KF + r * 4);
            float2 v = *(const float2*)(cb + k * D_DIM + dpos);
            *(float2*)(ob + (long long)r * D_DIM) = v;
        }
    }
    __syncthreads();

    // ---- fused exact refinement of near-tie rows (~0.2% of rows at TAU=0.01)
    for (int r = wid; r < BM; r += 8) {
        if (!flg[r]) continue;                      // warp-uniform branch
        const long long row = row0 + r;
        const float* zr = z + row * D_DIM;
        float zreg[16];
        #pragma unroll
        for (int t = 0; t < 16; ++t) {
            int d = lane + t * 32;
            zreg[t] = (d < D_DIM) ? zr[d] : 0.f;
        }
        float bv = 3.4e38f;
        int bk = 0;
        for (int c = 0; c < K_CODES; ++c) {
            const float* cr = cb + c * D_DIM;
            float s = 0.f;
            #pragma unroll
            for (int t = 0; t < 16; ++t) {
                int d = lane + t * 32;
                float cv = (d < D_DIM) ? cr[d] : 0.f;
                s = fmaf(zreg[t], cv, s);
            }
            #pragma unroll
            for (int off = 16; off; off >>= 1)
                s += __shfl_xor_sync(0xffffffffu, s, off);
            float d2 = fmaf(-2.f, s, csq_s[c]);
            if (d2 < bv) { bv = d2; bk = c; }       // strict <: lowest index wins ties
        }
        for (int d = lane; d < D_DIM; d += 32)
            out[row * D_DIM + d] = cb[bk * D_DIM + d];
    }
}

// ---------------------------------------------------------------- launch
extern "C" void kernel_launch(void* const* d_in, const int* in_sizes, int n_in,
                              void* d_out, int out_size) {
    const float* z  = (const float*)d_in[0];
    const float* cb = (const float*)d_in[1];
    float* out = (float*)d_out;

    cudaFuncSetAttribute(vq_mma_kernel, cudaFuncAttributeMaxDynamicSharedMemorySize,
                         SMEM_BYTES);

    const int n_rows  = in_sizes[0] / D_DIM;   // 131072
    const int nblocks = n_rows / BM;           // 1024

    prep_kernel<<<K_CODES, 256>>>(cb);
    vq_mma_kernel<<<nblocks, 256, SMEM_BYTES>>>(z, cb, out);
}

// round 16
// speedup vs baseline: 3.4842x; 1.3451x over previous
#include <cuda_runtime.h>
#include <cuda_bf16.h>
#include <cstdint>

// VQ lookup via warp-level bf16 mma.sync (HMMA) + candidate-limited exact refine.
// R15: SINGLE-pass approx  dot ~= zh*ch  (both sides bf16-rounded once).
//   |err| in dist2 <= ~0.27 (max over all pairs); TAU=1.0 > 2*max.
//   Rows with top-2 gap < TAU are re-decided EXACTLY, but only over the
//   candidate codes whose approx d2 <= bv+TAU (typically 2-4 codes).
// Structure = R9/R12 (proven 2 CTAs/SM phase-serial loop), 1/3 of the MMAs.

#define D_DIM   510
#define K_CODES 128
#define BM      128
#define KC      64           // K-chunk (elements)
#define NCH     8            // 8*64 = 512, cols 510/511 zeroed
#define TAU     1.0f
#define NCAND   8
#define ST      144          // bf16 tile row stride BYTES (72 bf16)

// smem byte offsets
#define SM_CSQ  0                        // 128 f32
#define SM_KF   512                      // 128 i32
#define SM_FLG  1024                     // 128 i32
#define SM_BV   1536                     // 2*128 f32
#define SM_SV   2560                     // 2*128 f32
#define SM_BK   3584                     // 2*128 i32
#define SM_CNT  4608                     // 128 i32
#define SM_RBV  5120                     // 128 f32
#define SM_CAND 5632                     // 128*8 i32
#define SM_ZH   9728                     // 128*144
#define SM_CH   (SM_ZH + 128*ST)
#define SMEM_BYTES (SM_CH + 128*ST)      // 46592 -> 2 CTAs/SM easily

__device__ float g_csq[K_CODES];
__device__ __align__(128) __nv_bfloat16 g_cbh[K_CODES * 512];  // 512-padded rows

// ---------------------------------------------------------------- prep: c_sq + cb bf16
__global__ void prep_kernel(const float* __restrict__ cb) {
    int k = blockIdx.x, tid = threadIdx.x;
    float s = 0.f;
    for (int d = tid; d < 512; d += 256) {
        float v = (d < D_DIM) ? cb[k * D_DIM + d] : 0.f;
        g_cbh[k * 512 + d] = __float2bfloat16(v);
        s = fmaf(v, v, s);
    }
    #pragma unroll
    for (int off = 16; off; off >>= 1) s += __shfl_xor_sync(0xffffffffu, s, off);
    __shared__ float red[8];
    if ((tid & 31) == 0) red[tid >> 5] = s;
    __syncthreads();
    if (tid == 0) {
        float t = 0.f;
        #pragma unroll
        for (int i = 0; i < 8; i++) t += red[i];
        g_csq[k] = t;
    }
}

// ---------------------------------------------------------------- helpers
__device__ __forceinline__ uint32_t pack2(__nv_bfloat16 a, __nv_bfloat16 b) {
    return (uint32_t)__bfloat16_as_ushort(b) << 16 | (uint32_t)__bfloat16_as_ushort(a);
}
__device__ __forceinline__ void ldm4(uint32_t* r, uint32_t addr) {
    asm volatile("ldmatrix.sync.aligned.m8n8.x4.shared.b16 {%0,%1,%2,%3}, [%4];"
                 : "=r"(r[0]), "=r"(r[1]), "=r"(r[2]), "=r"(r[3]) : "r"(addr));
}
__device__ __forceinline__ void mma16816(float* d, const uint32_t* a,
                                         const uint32_t* b) {
    asm volatile(
        "mma.sync.aligned.m16n8k16.row.col.f32.bf16.bf16.f32 "
        "{%0,%1,%2,%3}, {%4,%5,%6,%7}, {%8,%9}, {%0,%1,%2,%3};"
        : "+f"(d[0]), "+f"(d[1]), "+f"(d[2]), "+f"(d[3])
        : "r"(a[0]), "r"(a[1]), "r"(a[2]), "r"(a[3]), "r"(b[0]), "r"(b[1]));
}
__device__ __forceinline__ void merge2(float& bv, float& sv, int& bk,
                                       float obv, float osv, int obk) {
    if (obv < bv) { sv = fminf(bv, osv); bv = obv; bk = obk; }
    else          { sv = fminf(sv, obv); }
}

extern __shared__ __align__(128) char smem[];

// ---------------------------------------------------------------- main kernel
__global__ __launch_bounds__(256, 2)
void vq_mma_kernel(const float* __restrict__ z,
                   const float* __restrict__ cb,
                   float* __restrict__ out) {
    const uint32_t sbase = (uint32_t)__cvta_generic_to_shared(smem);
    const int tid  = threadIdx.x;
    const int wid  = tid >> 5;
    const int lane = tid & 31;
    const int wr   = wid & 3;       // row group: 4 x 32 rows
    const int wc   = wid >> 2;      // code group: 2 x 64 codes
    const long long row0 = (long long)blockIdx.x * BM;

    if (tid < K_CODES) *(float*)(smem + SM_CSQ + tid * 4) = g_csq[tid];

    const float* zg = z + row0 * D_DIM;

    float acc[2][8][4];
    #pragma unroll
    for (int mt = 0; mt < 2; ++mt)
        #pragma unroll
        for (int nt = 0; nt < 8; ++nt)
            #pragma unroll
            for (int q = 0; q < 4; ++q) acc[mt][nt][q] = 0.f;

    // ldmatrix lane->address geometry (byte offsets within a tile)
    const uint32_t a_off = (uint32_t)((wr * 32 + (lane & 15)) * ST + ((lane >> 4) * 8) * 2);
    const uint32_t b_off = (uint32_t)((wc * 64 + ((lane >> 4) << 3) + (lane & 7)) * ST
                                      + (((lane >> 3) & 1) * 8) * 2);
    // z load/convert geometry: 16 threads per row, 4 floats each
    const int lr0 = tid >> 4;
    const int lkq = (tid & 15) * 4;

    for (int ch = 0; ch < NCH; ++ch) {
        __syncthreads();             // tiles free (prev chunk's mma done)
        const int gk = ch * KC + lkq;
        const bool tail = (gk == 508);

        // ---- z tile: load fp32, round to bf16 (single-pass scheme)
        #pragma unroll
        for (int it = 0; it < 8; ++it) {
            const int r = lr0 + it * 16;
            const uint32_t so = (uint32_t)(r * ST + lkq * 2);
            const float* p = zg + (long long)r * D_DIM + gk;
            float2 a = *(const float2*)p;
            float2 b = tail ? make_float2(0.f, 0.f) : *(const float2*)(p + 2);
            __nv_bfloat16 h0 = __float2bfloat16(a.x);
            __nv_bfloat16 h1 = __float2bfloat16(a.y);
            __nv_bfloat16 h2 = __float2bfloat16(b.x);
            __nv_bfloat16 h3 = __float2bfloat16(b.y);
            *(uint2*)(smem + SM_ZH + so) = make_uint2(pack2(h0,h1), pack2(h2,h3));
        }
        // ---- cb tile: straight uint4 copy from pre-rounded global (L2-hot)
        #pragma unroll
        for (int it = 0; it < 4; ++it) {
            const int idx = it * 256 + tid;   // 0..1023
            const int r = idx >> 3;           // code row 0..127
            const int q = idx & 7;            // uint4 slot within 128B
            uint4 vh = *((const uint4*)(g_cbh + r * 512 + ch * KC) + q);
            *(uint4*)(smem + SM_CH + r * ST + q * 16) = vh;
        }
        __syncthreads();

        // ---- mma over 4 k-steps of 16: zh x ch (single pass)
        #pragma unroll
        for (int ks = 0; ks < 4; ++ks) {
            const uint32_t kb = (uint32_t)(ks * 32);   // 16 bf16 = 32 bytes
            uint32_t ah[2][4];
            #pragma unroll
            for (int mt = 0; mt < 2; ++mt)
                ldm4(ah[mt], sbase + SM_ZH + a_off + (uint32_t)(mt * 16 * ST) + kb);
            #pragma unroll
            for (int np = 0; np < 4; ++np) {           // n-tile pairs
                const uint32_t bo = b_off + (uint32_t)(np * 16 * ST) + kb;
                uint32_t bh[4];
                ldm4(bh, sbase + SM_CH + bo);
                #pragma unroll
                for (int mt = 0; mt < 2; ++mt) {
                    mma16816(acc[mt][np*2+0], ah[mt], bh + 0);
                    mma16816(acc[mt][np*2+1], ah[mt], bh + 2);
                }
            }
        }
    }

    // ---- epilogue: top-2 per row
    const float* csq_s = (const float*)(smem + SM_CSQ);
    float* bvp = (float*)(smem + SM_BV);
    float* svp = (float*)(smem + SM_SV);
    int*   bkp = (int*)(smem + SM_BK);
    int*   flg = (int*)(smem + SM_FLG);
    int*   cnt = (int*)(smem + SM_CNT);
    float* rbv = (float*)(smem + SM_RBV);
    int*   cand = (int*)(smem + SM_CAND);

    #pragma unroll
    for (int mt = 0; mt < 2; ++mt) {
        #pragma unroll
        for (int rh = 0; rh < 2; ++rh) {
            float bv = 3.4e38f, sv = 3.4e38f;
            int bk = 0;
            #pragma unroll
            for (int nt = 0; nt < 8; ++nt) {
                #pragma unroll
                for (int s = 0; s < 2; ++s) {
                    const int c = wc * 64 + nt * 8 + (lane & 3) * 2 + s;
                    const float d2 = fmaf(-2.f, acc[mt][nt][rh * 2 + s], csq_s[c]);
                    if (d2 < bv) { sv = bv; bv = d2; bk = c; }
                    else if (d2 < sv) sv = d2;
                }
            }
            #pragma unroll
            for (int off = 1; off <= 2; off <<= 1) {
                float obv = __shfl_xor_sync(0xffffffffu, bv, off);
                float osv = __shfl_xor_sync(0xffffffffu, sv, off);
                int   obk = __shfl_xor_sync(0xffffffffu, bk, off);
                merge2(bv, sv, bk, obv, osv, obk);
            }
            if ((lane & 3) == 0) {
                const int r = wr * 32 + mt * 16 + rh * 8 + (lane >> 2);
                bvp[wc * 128 + r] = bv;
                svp[wc * 128 + r] = sv;
                bkp[wc * 128 + r] = bk;
            }
        }
    }
    __syncthreads();

    if (tid < BM) {
        float bv = bvp[tid], sv = svp[tid];
        int bk = bkp[tid];
        merge2(bv, sv, bk, bvp[128 + tid], svp[128 + tid], bkp[128 + tid]);
        *(int*)(smem + SM_KF + tid * 4) = bk;
        flg[tid] = ((sv - bv) < TAU) ? 1 : 0;
        rbv[tid] = bv;
        cnt[tid] = 0;
    }
    __syncthreads();

    // ---- candidate collection for flagged rows (rescan registers)
    #pragma unroll
    for (int mt = 0; mt < 2; ++mt) {
        #pragma unroll
        for (int rh = 0; rh < 2; ++rh) {
            const int r = wr * 32 + mt * 16 + rh * 8 + (lane >> 2);
            if (!flg[r]) continue;
            const float thr = rbv[r] + TAU;
            #pragma unroll
            for (int nt = 0; nt < 8; ++nt) {
                #pragma unroll
                for (int s = 0; s < 2; ++s) {
                    const int c = wc * 64 + nt * 8 + (lane & 3) * 2 + s;
                    const float d2 = fmaf(-2.f, acc[mt][nt][rh * 2 + s], csq_s[c]);
                    if (d2 <= thr) {
                        int slot = atomicAdd(&cnt[r], 1);
                        if (slot < NCAND) cand[r * NCAND + slot] = c;
                    }
                }
            }
        }
    }

    // ---- gather: out[row] = codebook[kfin[row]]  (independent of rescan)
    if (tid < 255) {
        const int dpos = tid * 2;
        float* ob = out + row0 * D_DIM + dpos;
        #pragma unroll 4
        for (int r = 0; r < BM; ++r) {
            int k = *(const int*)(smem + SM_KF + r * 4);
            float2 v = *(const float2*)(cb + k * D_DIM + dpos);
            *(float2*)(ob + (long long)r * D_DIM) = v;
        }
    }
    __syncthreads();

    // ---- exact refine of flagged rows over their candidate sets (~5% rows)
    for (int r = wid; r < BM; r += 8) {
        if (!flg[r]) continue;                      // warp-uniform branch
        const long long row = row0 + r;
        const float* zr = z + row * D_DIM;
        float zreg[16];
        #pragma unroll
        for (int t = 0; t < 16; ++t) {
            int d = lane + t * 32;
            zreg[t] = (d < D_DIM) ? zr[d] : 0.f;
        }
        float bv = 3.4e38f;
        int bk = 1 << 30;
        const int n = cnt[r];
        const int m = (n > NCAND) ? K_CODES : n;    // overflow -> full scan
        for (int j = 0; j < m; ++j) {
            const int c = (n > NCAND) ? j : cand[r * NCAND + j];
            const float* cr = cb + c * D_DIM;
            float s = 0.f;
            #pragma unroll
            for (int t = 0; t < 16; ++t) {
                int d = lane + t * 32;
                float cv = (d < D_DIM) ? cr[d] : 0.f;
                s = fmaf(zreg[t], cv, s);
            }
            #pragma unroll
            for (int off = 16; off; off >>= 1)
                s += __shfl_xor_sync(0xffffffffu, s, off);
            float d2 = fmaf(-2.f, s, csq_s[c]);
            if (d2 < bv || (d2 == bv && c < bk)) { bv = d2; bk = c; }
        }
        for (int d = lane; d < D_DIM; d += 32)
            out[row * D_DIM + d] = cb[bk * D_DIM + d];
    }
}

// ---------------------------------------------------------------- launch
extern "C" void kernel_launch(void* const* d_in, const int* in_sizes, int n_in,
                              void* d_out, int out_size) {
    const float* z  = (const float*)d_in[0];
    const float* cb = (const float*)d_in[1];
    float* out = (float*)d_out;

    cudaFuncSetAttribute(vq_mma_kernel, cudaFuncAttributeMaxDynamicSharedMemorySize,
                         SMEM_BYTES);

    const int n_rows  = in_sizes[0] / D_DIM;   // 131072
    const int nblocks = n_rows / BM;           // 1024

    prep_kernel<<<K_CODES, 256>>>(cb);
    vq_mma_kernel<<<nblocks, 256, SMEM_BYTES>>>(z, cb, out);
}